// round 7
// baseline (speedup 1.0000x reference)
#include <cuda_runtime.h>

// StoutSmearSlice: 24^4 lattice, 4 dirs, 3x3 complex links (separate re/im fp32).
// MU=0, update EVEN parity sites of dir 0; everything else is a copy.
//
// Round 7: R4 structure (sequential roles, proven best) + float4-window matrix
// loads: 3 LDG.128 per array per matrix (was 5 LDG.64), cutting L1 wavefronts
// ~1.67x on the dominant strided-load term. 2-level FSEL select on alu pipe.

#define IDX9(d,t,z,y,x) ((((((d)*24+(t))*24+(z))*24+(y))*24+(x))*9)

static const int NSITE  = 24 * 24 * 24 * 12;          // even sites = 165888
static const int NCB    = NSITE / 128;                // 1296 compute blocks
static const int DIR_F  = 24 * 24 * 24 * 24 * 9;      // floats per direction
static const int COPY4  = 3 * DIR_F / 4;              // float4s in dirs 1..3
static const int PER_B  = 128 * 4;                    // float4s per copy block
static const int NCPB   = COPY4 / PER_B;              // 4374 dirs1-3 copy blocks
static const int NODD_E = NSITE * 9;                  // odd dir0 complex elements
static const int NODDB  = NODD_E / (128 * 4);         // 2916 odd-copy blocks

typedef unsigned long long c64;   // packed {lo=re, hi=im} fp32 pair

__device__ __forceinline__ c64 pk(float lo, float hi) {
    c64 r; asm("mov.b64 %0,{%1,%2};" : "=l"(r) : "f"(lo), "f"(hi)); return r;
}
__device__ __forceinline__ void upk(c64 v, float &lo, float &hi) {
    asm("mov.b64 {%0,%1},%2;" : "=f"(lo), "=f"(hi) : "l"(v));
}
__device__ __forceinline__ c64 fma2(c64 a, c64 b, c64 c) {
    c64 d; asm("fma.rn.f32x2 %0,%1,%2,%3;" : "=l"(d) : "l"(a), "l"(b), "l"(c));
    return d;
}
__device__ __forceinline__ c64 mul2(c64 a, c64 b) {
    c64 d; asm("mul.rn.f32x2 %0,%1,%2;" : "=l"(d) : "l"(a), "l"(b)); return d;
}

struct C3 { c64 m[9]; };

// Float4-window load: a = b & ~3 is 16B-aligned; [a, a+12) covers [b, b+9).
// 3 LDG.128 per array + 2-level select. Last matrix starts at b%4==3, so the
// window never reads past the array end.
__device__ __forceinline__ void mload(C3 &A, const float* __restrict__ re,
                                      const float* __restrict__ im, int b) {
    int a = b & ~3;
    int off = b & 3;
    bool p0 = (off & 1) != 0;
    bool p1 = (off & 2) != 0;
    const float4* r4 = (const float4*)(re + a);
    const float4* i4 = (const float4*)(im + a);
    float fr[12], fi[12];
#pragma unroll
    for (int j = 0; j < 3; j++) {
        float4 vr = r4[j], vi = i4[j];
        fr[4*j] = vr.x; fr[4*j+1] = vr.y; fr[4*j+2] = vr.z; fr[4*j+3] = vr.w;
        fi[4*j] = vi.x; fi[4*j+1] = vi.y; fi[4*j+2] = vi.z; fi[4*j+3] = vi.w;
    }
#pragma unroll
    for (int i = 0; i < 9; i++) {
        float r0 = p0 ? fr[i+1] : fr[i];
        float r2 = p0 ? fr[i+3] : fr[i+2];
        float m0 = p0 ? fi[i+1] : fi[i];
        float m2 = p0 ? fi[i+3] : fi[i+2];
        A.m[i] = pk(p1 ? r2 : r0, p1 ? m2 : m0);
    }
}

// MODE: 0 = A@B, 1 = A@B^dag, 2 = A^dag@B
template <int MODE>
__device__ __forceinline__ void cmul(C3 &C, const C3 &A, const C3 &B) {
#pragma unroll
    for (int r = 0; r < 3; r++) {
        float ar[3], ai[3];
#pragma unroll
        for (int k = 0; k < 3; k++)
            upk(A.m[MODE == 2 ? k * 3 + r : r * 3 + k], ar[k], ai[k]);
        c64 arr[3], aii[3];
#pragma unroll
        for (int k = 0; k < 3; k++) { arr[k] = pk(ar[k], ar[k]); aii[k] = pk(ai[k], ai[k]); }
#pragma unroll
        for (int c = 0; c < 3; c++) {
            c64 b0 = B.m[MODE == 1 ? c * 3 + 0 : 0 * 3 + c];
            c64 acc1 = mul2(arr[0], b0);
            c64 acc2 = mul2(aii[0], b0);
#pragma unroll
            for (int k = 1; k < 3; k++) {
                c64 b = B.m[MODE == 1 ? c * 3 + k : k * 3 + c];
                acc1 = fma2(arr[k], b, acc1);
                acc2 = fma2(aii[k], b, acc2);
            }
            float x1, y1, x2, y2;
            upk(acc1, x1, y1); upk(acc2, x2, y2);
            float cr, ci;
            if (MODE == 0)      { cr = x1 - y2; ci = y1 + x2; }
            else if (MODE == 1) { cr = x1 + y2; ci = x2 - y1; }
            else                { cr = x1 + y2; ci = y1 - x2; }
            C.m[r * 3 + c] = pk(cr, ci);
        }
    }
}

__device__ __forceinline__ void macc(C3 &F, const C3 &T, float c) {
    c64 cc = pk(c, c);
#pragma unroll
    for (int i = 0; i < 9; i++) F.m[i] = fma2(cc, T.m[i], F.m[i]);
}

// Forward staple (cf) + backward staple (cb) for one nu direction.
__device__ __forceinline__ void staple_pair(C3 &f,
        const float* __restrict__ xre, const float* __restrict__ xim,
        int b0p, int b0m, int bns, int bnsmu, int bnm, int bnmmu,
        float cf, float cb) {
    C3 A, B, C, T1, T2;
    mload(A, xre, xim, b0p);        // U0(s+nu)
    mload(B, xre, xim, bnsmu);      // Unu(s+mu)
    cmul<1>(T1, A, B);              // U0(s+nu) @ Unu(s+mu)^dag
    mload(C, xre, xim, bns);        // Unu(s)
    cmul<0>(T2, C, T1);
    macc(f, T2, cf);

    mload(A, xre, xim, bnm);        // Unu(s-nu)
    mload(B, xre, xim, b0m);        // U0(s-nu)
    cmul<2>(T1, A, B);              // Unu(s-nu)^dag @ U0(s-nu)
    mload(C, xre, xim, bnmmu);      // Unu(s-nu+mu)
    cmul<0>(T2, T1, C);
    macc(f, T2, cb);
}

__global__ __launch_bounds__(128) void stout_fused(
        const float* __restrict__ xre,
        const float* __restrict__ xim,
        const float* __restrict__ coeff,
        float2* __restrict__ out) {
    if (blockIdx.x >= NCB) {
        int rb = blockIdx.x - NCB;
        if (rb < NCPB) {
            // ---- copy role: dirs 1..3, float4 interleave ----
            const float4* re4 = (const float4*)(xre + DIR_F);
            const float4* im4 = (const float4*)(xim + DIR_F);
            float4* o4 = (float4*)(out + DIR_F);
            int base = rb * PER_B + threadIdx.x;
#pragma unroll
            for (int k = 0; k < 4; k++) {
                int i = base + k * 128;
                float4 r = re4[i], m = im4[i];
                o4[2*i]     = make_float4(r.x, m.x, r.y, m.y);
                o4[2*i + 1] = make_float4(r.z, m.z, r.w, m.w);
            }
        } else {
            // ---- odd-site dir-0 copy role ----
            int base = (rb - NCPB) * (128 * 4) + threadIdx.x;
#pragma unroll
            for (int k = 0; k < 4; k++) {
                int w = base + k * 128;          // odd-element linear index
                int s = w / 9, i = w - 9 * s;    // odd-site index, element
                int xi = s % 12; int r = s / 12;
                int y = r % 24; r /= 24;
                int z = r % 24; r /= 24;
                int t = r;
                int x = 2 * xi + (((t + z + y) & 1) ^ 1);   // odd parity
                int addr = IDX9(0, t, z, y, x) + i;
                out[addr] = make_float2(xre[addr], xim[addr]);
            }
        }
        return;
    }

    // ---- compute role: one even site ----
    int tid = blockIdx.x * 128 + threadIdx.x;
    int xi = tid % 12; int r = tid / 12;
    int y = r % 24; r /= 24;
    int z = r % 24; r /= 24;
    int t = r;
    int x = 2 * xi + ((t + z + y) & 1);      // (t+z+y+x) even

    c64* out64 = (c64*)out;

    int tp = (t + 1) % 24;
    int zp = (z + 1) % 24, zm = (z + 23) % 24;
    int yp = (y + 1) % 24, ym = (y + 23) % 24;
    int xp = (x + 1) % 24, xm = (x + 23) % 24;

    // scale_coeff(coeff,0.75) with the /6 staple average folded in
    float c[6];
#pragma unroll
    for (int i = 0; i < 6; i++)
        c[i] = (0.47746482927568606f / 6.0f) * atanf(coeff[i]);

    C3 f;
#pragma unroll
    for (int i = 0; i < 9; i++) f.m[i] = 0ull;

    staple_pair(f, xre, xim,                     // nu = 1 (Z)
                IDX9(0,t,zp,y,x), IDX9(0,t,zm,y,x),
                IDX9(1,t,z,y,x),  IDX9(1,tp,z,y,x),
                IDX9(1,t,zm,y,x), IDX9(1,tp,zm,y,x),
                c[0], c[1]);
    staple_pair(f, xre, xim,                     // nu = 2 (Y)
                IDX9(0,t,z,yp,x), IDX9(0,t,z,ym,x),
                IDX9(2,t,z,y,x),  IDX9(2,tp,z,y,x),
                IDX9(2,t,z,ym,x), IDX9(2,tp,z,ym,x),
                c[2], c[3]);
    staple_pair(f, xre, xim,                     // nu = 3 (X)
                IDX9(0,t,z,y,xp), IDX9(0,t,z,y,xm),
                IDX9(3,t,z,y,x),  IDX9(3,tp,z,y,x),
                IDX9(3,t,z,y,xm), IDX9(3,tp,z,y,xm),
                c[4], c[5]);

    int b0 = IDX9(0, t, z, y, x);
    C3 U0; mload(U0, xre, xim, b0);

    // Z = projectTangent(f @ U0^dag) scaled by 2^-4
    C3 Mm; cmul<1>(Mm, f, U0);
    float mr[9], mi[9];
#pragma unroll
    for (int i = 0; i < 9; i++) upk(Mm.m[i], mr[i], mi[i]);
    const float s = 0.03125f;   // 0.5 * 2^-4
    float zre[9], zim[9];
#pragma unroll
    for (int rr = 0; rr < 3; rr++)
#pragma unroll
        for (int cc = 0; cc < 3; cc++) {
            zre[rr*3+cc] = s * (mr[rr*3+cc] - mr[cc*3+rr]);
            zim[rr*3+cc] = s * (mi[rr*3+cc] + mi[cc*3+rr]);
        }
    float tri = (zim[0] + zim[4] + zim[8]) * (1.0f / 3.0f);
    zim[0] -= tri; zim[4] -= tri; zim[8] -= tri;
    C3 Z;
#pragma unroll
    for (int i = 0; i < 9; i++) Z.m[i] = pk(zre[i], zim[i]);

    // Horner Taylor, 12 terms: E = I + (Z@E)/k
    const c64 one = pk(1.0f, 0.0f);
    C3 E, T1;
#pragma unroll
    for (int i = 0; i < 9; i++) E.m[i] = (i % 4 == 0) ? one : 0ull;
#pragma unroll
    for (int k = 12; k >= 1; k--) {
        cmul<0>(T1, Z, E);
        float inv = 1.0f / (float)k;
        c64 inv2 = pk(inv, inv);
#pragma unroll
        for (int i = 0; i < 9; i++)
            E.m[i] = fma2(T1.m[i], inv2, (i % 4 == 0) ? one : 0ull);
    }
    // 4 squarings
#pragma unroll
    for (int sq = 0; sq < 4; sq++) { cmul<0>(T1, E, E); E = T1; }

    // y_mu = E @ U0 (even sites: xmu_fix = 0)
    C3 Y; cmul<0>(Y, E, U0);
#pragma unroll
    for (int i = 0; i < 9; i++) out64[b0 + i] = Y.m[i];
}

extern "C" void kernel_launch(void* const* d_in, const int* in_sizes, int n_in,
                              void* d_out, int out_size) {
    const float* xre   = (const float*)d_in[0];
    const float* xim   = (const float*)d_in[1];
    const float* coeff = (const float*)d_in[2];

    stout_fused<<<NCB + NCPB + NODDB, 128>>>(xre, xim, coeff, (float2*)d_out);
}

// round 8
// speedup vs baseline: 1.0456x; 1.0456x over previous
#include <cuda_runtime.h>

// StoutSmearSlice: 24^4 lattice, 4 dirs, 3x3 complex links (separate re/im fp32).
// MU=0, update EVEN parity sites of dir 0; everything else is a copy.
//
// Round 8: warp-cooperative SMEM staging. A warp owns 2 full y-rows (24 even
// sites; lanes 24-31 idle for math). Every matrix set is a full contiguous
// lattice row pair: staged with coalesced LDG.128 -> STS.128 (re/im interleaved
// c64), consumed with 9 LDS.64 per matrix. x-shifts/wraps are in-row indexing.
// The warp also writes the full 2-row dir0 output region (even computed + odd
// copied from the staged center set) with coalesced STG.128 -> the odd-copy
// role disappears entirely.

#define IDX9(d,t,z,y,x) ((((((d)*24+(t))*24+(z))*24+(y))*24+(x))*9)
#define RB(d,tt,zz,yy)  IDX9(d,tt,zz,yy,0)

static const int NCB    = 24 * 24 * 3;                // 1728 compute blocks (8 rows each)
static const int DIR_F  = 24 * 24 * 24 * 24 * 9;      // floats per direction
static const int COPY4  = 3 * DIR_F / 4;              // float4s in dirs 1..3
static const int PER_B  = 128 * 4;                    // float4s per copy block
static const int NCPB   = COPY4 / PER_B;              // 4374 dirs1-3 copy blocks

typedef unsigned long long c64;   // packed {lo=re, hi=im} fp32 pair

__device__ __forceinline__ c64 pk(float lo, float hi) {
    c64 r; asm("mov.b64 %0,{%1,%2};" : "=l"(r) : "f"(lo), "f"(hi)); return r;
}
__device__ __forceinline__ void upk(c64 v, float &lo, float &hi) {
    asm("mov.b64 {%0,%1},%2;" : "=f"(lo), "=f"(hi) : "l"(v));
}
__device__ __forceinline__ c64 fma2(c64 a, c64 b, c64 c) {
    c64 d; asm("fma.rn.f32x2 %0,%1,%2,%3;" : "=l"(d) : "l"(a), "l"(b), "l"(c));
    return d;
}
__device__ __forceinline__ c64 mul2(c64 a, c64 b) {
    c64 d; asm("mul.rn.f32x2 %0,%1,%2;" : "=l"(d) : "l"(a), "l"(b)); return d;
}

struct C3 { c64 m[9]; };

// MODE: 0 = A@B, 1 = A@B^dag, 2 = A^dag@B
template <int MODE>
__device__ __forceinline__ void cmul(C3 &C, const C3 &A, const C3 &B) {
#pragma unroll
    for (int r = 0; r < 3; r++) {
        float ar[3], ai[3];
#pragma unroll
        for (int k = 0; k < 3; k++)
            upk(A.m[MODE == 2 ? k * 3 + r : r * 3 + k], ar[k], ai[k]);
        c64 arr[3], aii[3];
#pragma unroll
        for (int k = 0; k < 3; k++) { arr[k] = pk(ar[k], ar[k]); aii[k] = pk(ai[k], ai[k]); }
#pragma unroll
        for (int c = 0; c < 3; c++) {
            c64 b0 = B.m[MODE == 1 ? c * 3 + 0 : 0 * 3 + c];
            c64 acc1 = mul2(arr[0], b0);
            c64 acc2 = mul2(aii[0], b0);
#pragma unroll
            for (int k = 1; k < 3; k++) {
                c64 b = B.m[MODE == 1 ? c * 3 + k : k * 3 + c];
                acc1 = fma2(arr[k], b, acc1);
                acc2 = fma2(aii[k], b, acc2);
            }
            float x1, y1, x2, y2;
            upk(acc1, x1, y1); upk(acc2, x2, y2);
            float cr, ci;
            if (MODE == 0)      { cr = x1 - y2; ci = y1 + x2; }
            else if (MODE == 1) { cr = x1 + y2; ci = x2 - y1; }
            else                { cr = x1 + y2; ci = y1 - x2; }
            C.m[r * 3 + c] = pk(cr, ci);
        }
    }
}

__device__ __forceinline__ void macc(C3 &F, const C3 &T, float c) {
    c64 cc = pk(c, c);
#pragma unroll
    for (int i = 0; i < 9; i++) F.m[i] = fma2(cc, T.m[i], F.m[i]);
}

// Stage 2 full lattice rows (216 complex each) of one (dir,t,z) into a warp
// buffer as interleaved c64. Coalesced: 108 float4 jobs per array across lanes.
__device__ __forceinline__ void stage(c64* __restrict__ sb,
        const float* __restrict__ xre, const float* __restrict__ xim,
        int gb0, int gb1, int lane) {
    __syncwarp();
#pragma unroll
    for (int kk = 0; kk < 4; kk++) {
        int j = kk * 32 + lane;
        if (j < 108) {
            int r  = j / 54;
            int cc = j - 54 * r;
            int g  = (r ? gb1 : gb0) + cc * 4;
            float4 vr = *(const float4*)(xre + g);
            float4 vi = *(const float4*)(xim + g);
            int s2 = r * 108 + cc * 2;          // float4 index into c64 buffer
            ((float4*)sb)[s2]     = make_float4(vr.x, vi.x, vr.y, vi.y);
            ((float4*)sb)[s2 + 1] = make_float4(vr.z, vi.z, vr.w, vi.w);
        }
    }
    __syncwarp();
}

__device__ __forceinline__ void extract(const c64* __restrict__ sb, int q,
                                        int mx, C3 &A) {
    int base = q * 216 + mx * 9;
#pragma unroll
    for (int i = 0; i < 9; i++) A.m[i] = sb[base + i];
}

__global__ __launch_bounds__(128) void stout_fused(
        const float* __restrict__ xre,
        const float* __restrict__ xim,
        const float* __restrict__ coeff,
        float2* __restrict__ out) {
    __shared__ c64 sbuf[4][2][432];

    if (blockIdx.x >= NCB) {
        // ---- copy role: dirs 1..3, float4 interleave ----
        int rb = blockIdx.x - NCB;
        const float4* re4 = (const float4*)(xre + DIR_F);
        const float4* im4 = (const float4*)(xim + DIR_F);
        float4* o4 = (float4*)(out + DIR_F);
        int base = rb * PER_B + threadIdx.x;
#pragma unroll
        for (int k = 0; k < 4; k++) {
            int i = base + k * 128;
            float4 r = re4[i], m = im4[i];
            o4[2*i]     = make_float4(r.x, m.x, r.y, m.y);
            o4[2*i + 1] = make_float4(r.z, m.z, r.w, m.w);
        }
        return;
    }

    // ---- compute role: warp = 2 y-rows at fixed (t,z) ----
    int zt   = blockIdx.x / 3;
    int yblk = blockIdx.x - 3 * zt;
    int t = zt / 24, z = zt - 24 * (zt / 24);
    int wi   = threadIdx.x >> 5;
    int lane = threadIdx.x & 31;
    int y0 = yblk * 8 + wi * 2;                 // rows y0, y0+1 (y0 <= 22)

    c64* b0 = sbuf[wi][0];
    c64* b1 = sbuf[wi][1];

    int q  = lane / 12; if (q > 1) q = 1;       // row within pair
    int xi = lane % 12;
    int y  = y0 + q;
    int p  = (t + z + y) & 1;
    int x  = 2 * xi + p;                        // even site
    int xp_ = (x + 1) % 24, xm_ = (x + 23) % 24;
    bool active = lane < 24;

    int tp = (t + 1) % 24;
    int zp = (z + 1) % 24, zm = (z + 23) % 24;
    int y1 = y0 + 1, yp2 = (y0 + 2) % 24, ym = (y0 + 23) % 24;

    float c[6];
#pragma unroll
    for (int i = 0; i < 6; i++)
        c[i] = (0.47746482927568606f / 6.0f) * atanf(coeff[i]);

    C3 f;
#pragma unroll
    for (int i = 0; i < 9; i++) f.m[i] = 0ull;

    C3 A, B, T1, T2;

    // ---- nu = 1 (Z) forward: x1(s) @ [U0(s+z) @ x1(s+t)^dag] ----
    stage(b0, xre, xim, RB(0,t,zp,y0), RB(0,t,zp,y1), lane);
    extract(b0, q, x, A);                       // U0(s+z)
    stage(b1, xre, xim, RB(1,tp,z,y0), RB(1,tp,z,y1), lane);
    extract(b1, q, x, B);                       // x1(s+t)
    cmul<1>(T1, A, B);
    stage(b0, xre, xim, RB(1,t,z,y0), RB(1,t,z,y1), lane);
    extract(b0, q, x, A);                       // x1(s)
    cmul<0>(T2, A, T1);
    macc(f, T2, c[0]);

    // ---- nu = 1 backward: [x1(s-z)^dag @ U0(s-z)] @ x1(s-z+t) ----
    stage(b0, xre, xim, RB(1,t,zm,y0), RB(1,t,zm,y1), lane);
    extract(b0, q, x, A);                       // x1(s-z)
    stage(b1, xre, xim, RB(0,t,zm,y0), RB(0,t,zm,y1), lane);
    extract(b1, q, x, B);                       // U0(s-z)
    cmul<2>(T1, A, B);
    stage(b0, xre, xim, RB(1,tp,zm,y0), RB(1,tp,zm,y1), lane);
    extract(b0, q, x, B);                       // x1(s-z+t)
    cmul<0>(T2, T1, B);
    macc(f, T2, c[1]);

    // ---- nu = 2 (Y) forward ----
    stage(b0, xre, xim, RB(0,t,z,y1), RB(0,t,z,yp2), lane);
    extract(b0, q, x, A);                       // U0(s+y)
    stage(b1, xre, xim, RB(2,tp,z,y0), RB(2,tp,z,y1), lane);
    extract(b1, q, x, B);                       // x2(s+t)
    cmul<1>(T1, A, B);
    stage(b0, xre, xim, RB(2,t,z,y0), RB(2,t,z,y1), lane);
    extract(b0, q, x, A);                       // x2(s)
    cmul<0>(T2, A, T1);
    macc(f, T2, c[2]);

    // ---- nu = 2 backward ----
    stage(b0, xre, xim, RB(2,t,z,ym), RB(2,t,z,y0), lane);
    extract(b0, q, x, A);                       // x2(s-y)
    stage(b1, xre, xim, RB(0,t,z,ym), RB(0,t,z,y0), lane);
    extract(b1, q, x, B);                       // U0(s-y)
    cmul<2>(T1, A, B);
    stage(b0, xre, xim, RB(2,tp,z,ym), RB(2,tp,z,y0), lane);
    extract(b0, q, x, B);                       // x2(s-y+t)
    cmul<0>(T2, T1, B);
    macc(f, T2, c[3]);

    // ---- nu = 3 (X): pin dir0 center rows in b0 ----
    stage(b0, xre, xim, RB(0,t,z,y0), RB(0,t,z,y1), lane);   // U0 center rows
    stage(b1, xre, xim, RB(3,t,z,y0), RB(3,t,z,y1), lane);   // x3 center rows
    C3 T1b;
    extract(b0, q, xp_, A);                     // U0(s+x)
    extract(b1, q, x,   B);                     // x3(s)
    cmul<0>(T1, B, A);                          // x3(s) @ U0(s+x)
    extract(b0, q, xm_, A);                     // U0(s-x)
    extract(b1, q, xm_, B);                     // x3(s-x)
    cmul<2>(T1b, B, A);                         // x3(s-x)^dag @ U0(s-x)
    stage(b1, xre, xim, RB(3,tp,z,y0), RB(3,tp,z,y1), lane); // x3 at t+1
    extract(b1, q, x, B);                       // x3(s+t)
    cmul<1>(T2, T1, B);
    macc(f, T2, c[4]);
    extract(b1, q, xm_, B);                     // x3(s-x+t)
    cmul<0>(T2, T1b, B);
    macc(f, T2, c[5]);

    // ---- U0 + projection + matexp ----
    C3 U0; extract(b0, q, x, U0);
    C3 Mm; cmul<1>(Mm, f, U0);                  // M = f @ U0^dag
    float mr[9], mi[9];
#pragma unroll
    for (int i = 0; i < 9; i++) upk(Mm.m[i], mr[i], mi[i]);
    const float s = 0.03125f;                   // 0.5 * 2^-4
    float zre[9], zim[9];
#pragma unroll
    for (int rr = 0; rr < 3; rr++)
#pragma unroll
        for (int cc = 0; cc < 3; cc++) {
            zre[rr*3+cc] = s * (mr[rr*3+cc] - mr[cc*3+rr]);
            zim[rr*3+cc] = s * (mi[rr*3+cc] + mi[cc*3+rr]);
        }
    float tri = (zim[0] + zim[4] + zim[8]) * (1.0f / 3.0f);
    zim[0] -= tri; zim[4] -= tri; zim[8] -= tri;
    C3 Z;
#pragma unroll
    for (int i = 0; i < 9; i++) Z.m[i] = pk(zre[i], zim[i]);

    const c64 one = pk(1.0f, 0.0f);
    C3 E;
#pragma unroll
    for (int i = 0; i < 9; i++) E.m[i] = (i % 4 == 0) ? one : 0ull;
#pragma unroll
    for (int k = 12; k >= 1; k--) {
        cmul<0>(T1, Z, E);
        float inv = 1.0f / (float)k;
        c64 inv2 = pk(inv, inv);
#pragma unroll
        for (int i = 0; i < 9; i++)
            E.m[i] = fma2(T1.m[i], inv2, (i % 4 == 0) ? one : 0ull);
    }
#pragma unroll
    for (int sq = 0; sq < 4; sq++) { cmul<0>(T1, E, E); E = T1; }

    C3 Y; cmul<0>(Y, E, U0);                    // y_mu = E @ U0

    // ---- assemble full 2-row dir0 output in b1, then coalesced STG ----
    __syncwarp();
    if (active) {
        int be = q * 216 + x * 9;
        int bo = q * 216 + (2 * xi + (p ^ 1)) * 9;
#pragma unroll
        for (int i = 0; i < 9; i++) {
            b1[be + i] = Y.m[i];
            b1[bo + i] = b0[bo + i];            // odd partner: plain copy
        }
    }
    __syncwarp();
    int ob = RB(0, t, z, y0);                   // c64 base, 432 c64 contiguous
    float4* og = (float4*)(out + ob);
    const float4* sg = (const float4*)b1;
#pragma unroll
    for (int kk = 0; kk < 7; kk++) {
        int j = kk * 32 + lane;
        if (j < 216) og[j] = sg[j];
    }
}

extern "C" void kernel_launch(void* const* d_in, const int* in_sizes, int n_in,
                              void* d_out, int out_size) {
    const float* xre   = (const float*)d_in[0];
    const float* xim   = (const float*)d_in[1];
    const float* coeff = (const float*)d_in[2];

    stout_fused<<<NCB + NCPB, 128>>>(xre, xim, coeff, (float2*)d_out);
}